// round 5
// baseline (speedup 1.0000x reference)
#include <cuda_runtime.h>
#include <math.h>

#define T 4096
#define D 2048
#define H 128

// ---------------- scratch (device globals; no allocation allowed) ----------
__device__ __align__(256) float g_q[T * H];
__device__ __align__(256) float g_k[T * H];
__device__ __align__(256) float g_v[T * H];
__device__ __align__(256) float g_s[T * T];        // 64 MB scores/probs
__device__ __align__(256) float g_part[8][T * H];  // split-K partials for PV

// ---------------------------------------------------------------------------
// Kernel 1: QKV projection.  C[4096,64tile] = X[4096,2048] @ W^T (W:[128,2048])
// grid (64 m-tiles, 2 n-halves, 3 weights), 256 threads, BM=64 BN=64 BK=16,
// 4x4 micro-tile per thread. Both operands K-contiguous (NT gemm).
// ---------------------------------------------------------------------------
__global__ __launch_bounds__(256) void qkv_kernel(
    const float* __restrict__ x,
    const float* __restrict__ wq,
    const float* __restrict__ wk,
    const float* __restrict__ wv) {
  __shared__ __align__(16) float Xs[16][68];
  __shared__ __align__(16) float Ws[16][68];

  const int mt = blockIdx.x, nt = blockIdx.y, wsel = blockIdx.z;
  const float* __restrict__ W = (wsel == 0) ? wq : (wsel == 1) ? wk : wv;
  float* out = (wsel == 0) ? g_q : (wsel == 1) ? g_k : g_v;

  const int tid = threadIdx.x;
  const int tx = tid & 15, ty = tid >> 4;
  const int lr = tid >> 2;         // 0..63 row within tile
  const int lk = (tid & 3) << 2;   // 0,4,8,12 k within BK

  const float* xp = x + (mt * 64 + lr) * D + lk;
  const float* wp = W + (nt * 64 + lr) * D + lk;

  float acc[4][4] = {};

  for (int k0 = 0; k0 < D; k0 += 16) {
    float4 xa = *(const float4*)(xp + k0);
    float4 wa = *(const float4*)(wp + k0);
    Xs[lk + 0][lr] = xa.x; Xs[lk + 1][lr] = xa.y;
    Xs[lk + 2][lr] = xa.z; Xs[lk + 3][lr] = xa.w;
    Ws[lk + 0][lr] = wa.x; Ws[lk + 1][lr] = wa.y;
    Ws[lk + 2][lr] = wa.z; Ws[lk + 3][lr] = wa.w;
    __syncthreads();
#pragma unroll
    for (int k = 0; k < 16; k++) {
      float4 a = *(const float4*)&Xs[k][ty << 2];
      float4 b = *(const float4*)&Ws[k][tx << 2];
      float av[4] = {a.x, a.y, a.z, a.w};
      float bv[4] = {b.x, b.y, b.z, b.w};
#pragma unroll
      for (int mi = 0; mi < 4; mi++)
#pragma unroll
        for (int ni = 0; ni < 4; ni++) acc[mi][ni] += av[mi] * bv[ni];
    }
    __syncthreads();
  }

  float* op = out + (mt * 64 + (ty << 2)) * H + nt * 64 + (tx << 2);
#pragma unroll
  for (int mi = 0; mi < 4; mi++)
    *(float4*)(op + mi * H) =
        make_float4(acc[mi][0], acc[mi][1], acc[mi][2], acc[mi][3]);
}

// ---------------------------------------------------------------------------
// Kernel 2: S tile = Q_tile @ K_tile^T * scale, causal mask written as -inf.
// grid (j=64, i=64); upper-triangle blocks (j>i) exit immediately.
// 64x64 tile, K-dim 128 processed in two 64-wide smem chunks.
// ---------------------------------------------------------------------------
__global__ __launch_bounds__(256) void scores_kernel() {
  const int jt = blockIdx.x, it = blockIdx.y;
  if (jt > it) return;

  __shared__ __align__(16) float Qs[64][68];
  __shared__ __align__(16) float Ks[64][68];

  const int tid = threadIdx.x;
  const int tx = tid & 15, ty = tid >> 4;

  float acc[4][4] = {};

  for (int d0 = 0; d0 < H; d0 += 64) {
#pragma unroll
    for (int p = 0; p < 4; p++) {
      int f = tid + (p << 8);      // 0..1023 float4 slots
      int r = f >> 4;              // 0..63
      int dq = (f & 15) << 2;      // 0..60
      float4 qa = *(const float4*)(g_q + (it * 64 + r) * H + d0 + dq);
      Qs[dq + 0][r] = qa.x; Qs[dq + 1][r] = qa.y;
      Qs[dq + 2][r] = qa.z; Qs[dq + 3][r] = qa.w;
      float4 ka = *(const float4*)(g_k + (jt * 64 + r) * H + d0 + dq);
      Ks[dq + 0][r] = ka.x; Ks[dq + 1][r] = ka.y;
      Ks[dq + 2][r] = ka.z; Ks[dq + 3][r] = ka.w;
    }
    __syncthreads();
#pragma unroll
    for (int k = 0; k < 64; k++) {
      float4 a = *(const float4*)&Qs[k][ty << 2];
      float4 b = *(const float4*)&Ks[k][tx << 2];
      float av[4] = {a.x, a.y, a.z, a.w};
      float bv[4] = {b.x, b.y, b.z, b.w};
#pragma unroll
      for (int mi = 0; mi < 4; mi++)
#pragma unroll
        for (int ni = 0; ni < 4; ni++) acc[mi][ni] += av[mi] * bv[ni];
    }
    __syncthreads();
  }

  const float scale = 0.08838834764831845f;  // 1/sqrt(128)
  const float NEG_INF = -INFINITY;
#pragma unroll
  for (int mi = 0; mi < 4; mi++) {
    int t = it * 64 + (ty << 2) + mi;
    int u0 = jt * 64 + (tx << 2);
    float4 v;
    v.x = (u0 + 0 > t) ? NEG_INF : acc[mi][0] * scale;
    v.y = (u0 + 1 > t) ? NEG_INF : acc[mi][1] * scale;
    v.z = (u0 + 2 > t) ? NEG_INF : acc[mi][2] * scale;
    v.w = (u0 + 3 > t) ? NEG_INF : acc[mi][3] * scale;
    *(float4*)(g_s + t * T + u0) = v;
  }
}

// ---------------------------------------------------------------------------
// Kernel 3: row softmax over cols [0, (i+1)*64). One block per row.
// Values held in registers (<=16 per thread). Fixed reduction order.
// ---------------------------------------------------------------------------
__global__ __launch_bounds__(256) void softmax_kernel() {
  const int t = blockIdx.x;
  const int ncols = ((t >> 6) + 1) << 6;  // tile-aligned causal end
  float* row = g_s + t * T;
  const int tid = threadIdx.x;

  float vals[16];
  float lmax = -INFINITY;
#pragma unroll
  for (int p = 0; p < 16; p++) {
    int c = tid + (p << 8);
    float v = (c < ncols) ? row[c] : -INFINITY;
    vals[p] = v;
    lmax = fmaxf(lmax, v);
  }

  __shared__ float redm[8];
#pragma unroll
  for (int o = 16; o; o >>= 1) lmax = fmaxf(lmax, __shfl_xor_sync(~0u, lmax, o));
  if ((tid & 31) == 0) redm[tid >> 5] = lmax;
  __syncthreads();
  float m = redm[0];
#pragma unroll
  for (int wv = 1; wv < 8; wv++) m = fmaxf(m, redm[wv]);

  float lsum = 0.f;
#pragma unroll
  for (int p = 0; p < 16; p++) {
    float e = __expf(vals[p] - m);  // exp(-inf)=0 handles mask + padding
    vals[p] = e;
    lsum += e;
  }

  __shared__ float reds[8];
#pragma unroll
  for (int o = 16; o; o >>= 1) lsum += __shfl_xor_sync(~0u, lsum, o);
  if ((tid & 31) == 0) reds[tid >> 5] = lsum;
  __syncthreads();
  float s = 0.f;
#pragma unroll
  for (int wv = 0; wv < 8; wv++) s += reds[wv];

  float inv = 1.0f / s;
#pragma unroll
  for (int p = 0; p < 16; p++) {
    int c = tid + (p << 8);
    if (c < ncols) row[c] = vals[p] * inv;
  }
}

// ---------------------------------------------------------------------------
// Kernel 4: partial O = P @ V with split-K (chunks of 512 kv positions).
// grid (chunk=8, i-tile=64); empty (chunk beyond causal end) blocks exit.
// BM=64 BN=128 BK=16, 4x8 micro-tile (cols split tx*4 and 64+tx*4).
// ---------------------------------------------------------------------------
__global__ __launch_bounds__(256) void pv_kernel() {
  const int ch = blockIdx.x, it = blockIdx.y;
  const int kbeg = ch << 9;
  const int klim = (it + 1) << 6;
  if (kbeg >= klim) return;
  const int kend = min(kbeg + 512, klim);

  __shared__ __align__(16) float Ps[16][68];
  __shared__ __align__(16) float Vs[16][132];

  const int tid = threadIdx.x;
  const int tx = tid & 15, ty = tid >> 4;
  const int lr = tid >> 2, lk = (tid & 3) << 2;
  const int m0 = it << 6;

  float acc[4][8] = {};

  for (int k0 = kbeg; k0 < kend; k0 += 16) {
    float4 pa = *(const float4*)(g_s + (m0 + lr) * T + k0 + lk);
    Ps[lk + 0][lr] = pa.x; Ps[lk + 1][lr] = pa.y;
    Ps[lk + 2][lr] = pa.z; Ps[lk + 3][lr] = pa.w;
#pragma unroll
    for (int p = 0; p < 2; p++) {
      int f = tid + (p << 8);   // 0..511 float4 slots
      int kk = f >> 5;          // 0..15
      int n4 = (f & 31) << 2;   // 0..124
      *(float4*)&Vs[kk][n4] = *(const float4*)(g_v + (k0 + kk) * H + n4);
    }
    __syncthreads();
#pragma unroll
    for (int k = 0; k < 16; k++) {
      float4 a = *(const float4*)&Ps[k][ty << 2];
      float4 b0 = *(const float4*)&Vs[k][tx << 2];
      float4 b1 = *(const float4*)&Vs[k][64 + (tx << 2)];
      float av[4] = {a.x, a.y, a.z, a.w};
      float bv[8] = {b0.x, b0.y, b0.z, b0.w, b1.x, b1.y, b1.z, b1.w};
#pragma unroll
      for (int mi = 0; mi < 4; mi++)
#pragma unroll
        for (int ni = 0; ni < 8; ni++) acc[mi][ni] += av[mi] * bv[ni];
    }
    __syncthreads();
  }

  float* op = g_part[ch] + (m0 + (ty << 2)) * H + (tx << 2);
#pragma unroll
  for (int mi = 0; mi < 4; mi++) {
    *(float4*)(op + mi * H) =
        make_float4(acc[mi][0], acc[mi][1], acc[mi][2], acc[mi][3]);
    *(float4*)(op + mi * H + 64) =
        make_float4(acc[mi][4], acc[mi][5], acc[mi][6], acc[mi][7]);
  }
}

// ---------------------------------------------------------------------------
// Kernel 5: combine split-K partials (only the valid chunks per row).
// ---------------------------------------------------------------------------
__global__ __launch_bounds__(256) void reduce_kernel(float* __restrict__ out) {
  int idx = blockIdx.x * 256 + threadIdx.x;  // 0..524287
  int t = idx >> 7;                          // row
  int nch = (t >> 9) + 1;                    // floor(row/512)+1 valid chunks
  float s = 0.f;
  for (int c = 0; c < nch; c++) s += g_part[c][idx];
  out[idx] = s;
}

// ---------------------------------------------------------------------------
extern "C" void kernel_launch(void* const* d_in, const int* in_sizes, int n_in,
                              void* d_out, int out_size) {
  (void)in_sizes; (void)n_in; (void)out_size;
  const float* x  = (const float*)d_in[0];
  const float* wq = (const float*)d_in[1];
  const float* wk = (const float*)d_in[2];
  const float* wv = (const float*)d_in[3];
  float* out = (float*)d_out;

  qkv_kernel<<<dim3(64, 2, 3), 256>>>(x, wq, wk, wv);
  scores_kernel<<<dim3(64, 64), 256>>>();
  softmax_kernel<<<4096, 256>>>();
  pv_kernel<<<dim3(8, 64), 256>>>();
  reduce_kernel<<<2048, 256>>>(out);
}

// round 7
// speedup vs baseline: 2.3457x; 2.3457x over previous
#include <cuda_runtime.h>
#include <cuda_bf16.h>
#include <math.h>
#include <stdint.h>

#define T 4096
#define D 2048
#define H 128

// ---------------- scratch (device globals; no allocation allowed) ----------
__device__ __align__(256) __nv_bfloat16 g_xhi[T * D];
__device__ __align__(256) __nv_bfloat16 g_xlo[T * D];
__device__ __align__(256) __nv_bfloat16 g_whi[3 * H * D];
__device__ __align__(256) __nv_bfloat16 g_wlo[3 * H * D];
__device__ __align__(256) __nv_bfloat16 g_qhi[T * H];
__device__ __align__(256) __nv_bfloat16 g_qlo[T * H];
__device__ __align__(256) __nv_bfloat16 g_khi[T * H];
__device__ __align__(256) __nv_bfloat16 g_klo[T * H];
__device__ __align__(256) __nv_bfloat16 g_vhiT[H * T];  // [head][token]
__device__ __align__(256) __nv_bfloat16 g_vloT[H * T];
__device__ __align__(256) float g_s[(size_t)T * T];     // fp32 logits
__device__ __align__(256) __nv_bfloat16 g_phi[(size_t)T * T];
__device__ __align__(256) __nv_bfloat16 g_plo[(size_t)T * T];
__device__ __align__(256) float g_part[8][T * H];       // split-K partials

// ---------------------------- PTX helpers ----------------------------------
__device__ __forceinline__ uint32_t smem_u32(const void* p) {
  uint32_t a;
  asm("{ .reg .u64 t; cvta.to.shared.u64 t, %1; cvt.u32.u64 %0, t; }"
      : "=r"(a) : "l"(p));
  return a;
}

__device__ __forceinline__ void cp16(uint32_t dst, const void* src) {
  asm volatile("cp.async.cg.shared.global [%0], [%1], 16;" ::
               "r"(dst), "l"(src) : "memory");
}
#define CP_COMMIT() asm volatile("cp.async.commit_group;" ::: "memory")
#define CP_WAIT(n)  asm volatile("cp.async.wait_group %0;" :: "n"(n) : "memory")

__device__ __forceinline__ void ldsm4(uint32_t* r, uint32_t addr) {
  asm volatile(
      "ldmatrix.sync.aligned.m8n8.x4.shared.b16 {%0,%1,%2,%3}, [%4];"
      : "=r"(r[0]), "=r"(r[1]), "=r"(r[2]), "=r"(r[3]) : "r"(addr));
}

__device__ __forceinline__ void mma_bf16(float* c, const uint32_t* a,
                                         const uint32_t* b) {
  asm volatile(
      "mma.sync.aligned.m16n8k16.row.col.f32.bf16.bf16.f32 "
      "{%0,%1,%2,%3}, {%4,%5,%6,%7}, {%8,%9}, {%0,%1,%2,%3};"
      : "+f"(c[0]), "+f"(c[1]), "+f"(c[2]), "+f"(c[3])
      : "r"(a[0]), "r"(a[1]), "r"(a[2]), "r"(a[3]), "r"(b[0]), "r"(b[1]));
}

// ---------------------------- SMEM layout ----------------------------------
#define SPAD 72                         // bf16 row stride (144 B, conflict-free)
#define TILE_B (128 * SPAD * 2)         // 18432 B per 128x64 bf16 tile
#define OFF_AHI 0
#define OFF_ALO (TILE_B)
#define OFF_BHI (2 * TILE_B)
#define OFF_BLO (3 * TILE_B)
#define BUF_B (4 * TILE_B)              // one pipeline buffer
#define SMEM_BYTES (2 * BUF_B)          // 147456 B (double-buffered)

struct GemmArgs {
  const __nv_bfloat16 *ahi, *alo, *bhi, *blo;
  int arow0, astride, brow0, bstride, col0, nchunks;
};

// cp.async one K=64 chunk (4 tiles of 128x64) into buffer `buf`.
__device__ __forceinline__ void load_chunk(uint32_t sb, int buf,
                                           const GemmArgs& g, int c0) {
  const int tid = threadIdx.x;
  uint32_t dbase = sb + (buf ? BUF_B : 0);
#pragma unroll
  for (int t = 0; t < 4; t++) {
    const __nv_bfloat16* src = (t == 0) ? g.ahi : (t == 1) ? g.alo
                               : (t == 2) ? g.bhi : g.blo;
    int r0 = (t < 2) ? g.arow0 : g.brow0;
    int st = (t < 2) ? g.astride : g.bstride;
#pragma unroll
    for (int p = 0; p < 4; p++) {
      int i = tid + (p << 8);        // 0..1023 16B chunks
      int row = i >> 3;              // 0..127
      int col = (i & 7) << 3;        // bf16 col 0..56
      cp16(dbase + t * TILE_B + (uint32_t)(row * SPAD + col) * 2,
           src + (size_t)(r0 + row) * st + c0 + col);
    }
  }
}

// Mainloop: acc += Ahi*Bhi + Ahi*Blo + Alo*Bhi over all K chunks.
__device__ __forceinline__ void gemm_mainloop(float (&acc)[4][4][4],
                                              const GemmArgs& g, uint32_t sb) {
  const int tid = threadIdx.x;
  const int l = tid & 31, w = tid >> 5;
  const int wm = w & 1, wn = w >> 1;

  // ldmatrix lane address components (invariant across chunks)
  const uint32_t ra = (uint32_t)(wm * 64 + (l & 15));        // A row
  const uint32_t ka = (uint32_t)((l >> 4) << 3);             // A k sub-off
  const uint32_t rb = (uint32_t)(wn * 32 + (l & 7) + ((l >> 4) << 3));  // B row
  const uint32_t kb = (uint32_t)(((l >> 3) & 1) << 3);       // B k sub-off

  load_chunk(sb, 0, g, g.col0);
  CP_COMMIT();

  int buf = 0;
  for (int kc = 0; kc < g.nchunks; kc++) {
    bool has_next = (kc + 1 < g.nchunks);
    if (has_next) {
      load_chunk(sb, buf ^ 1, g, g.col0 + ((kc + 1) << 6));
      CP_COMMIT();
      CP_WAIT(1);
    } else {
      CP_WAIT(0);
    }
    __syncthreads();

    uint32_t base = sb + (buf ? BUF_B : 0);
#pragma unroll
    for (int ks = 0; ks < 4; ks++) {
      const uint32_t k0 = ks * 16;
      const uint32_t aHi = base + OFF_AHI + (ra * SPAD + k0 + ka) * 2;
      const uint32_t aLo = base + OFF_ALO + (ra * SPAD + k0 + ka) * 2;
      const uint32_t bHi = base + OFF_BHI + (rb * SPAD + k0 + kb) * 2;
      const uint32_t bLo = base + OFF_BLO + (rb * SPAD + k0 + kb) * 2;

      uint32_t a[4][4], b[2][4], b2[2][4];
#pragma unroll
      for (int mi = 0; mi < 4; mi++) ldsm4(a[mi], aHi + mi * 16 * SPAD * 2);
#pragma unroll
      for (int j = 0; j < 2; j++) ldsm4(b[j], bHi + j * 16 * SPAD * 2);
      // hi * hi
#pragma unroll
      for (int mi = 0; mi < 4; mi++)
#pragma unroll
        for (int nj = 0; nj < 4; nj++)
          mma_bf16(acc[mi][nj], a[mi], &b[nj >> 1][(nj & 1) << 1]);
      // hi * lo
#pragma unroll
      for (int j = 0; j < 2; j++) ldsm4(b2[j], bLo + j * 16 * SPAD * 2);
#pragma unroll
      for (int mi = 0; mi < 4; mi++)
#pragma unroll
        for (int nj = 0; nj < 4; nj++)
          mma_bf16(acc[mi][nj], a[mi], &b2[nj >> 1][(nj & 1) << 1]);
      // lo * hi
#pragma unroll
      for (int mi = 0; mi < 4; mi++) ldsm4(a[mi], aLo + mi * 16 * SPAD * 2);
#pragma unroll
      for (int mi = 0; mi < 4; mi++)
#pragma unroll
        for (int nj = 0; nj < 4; nj++)
          mma_bf16(acc[mi][nj], a[mi], &b[nj >> 1][(nj & 1) << 1]);
    }
    __syncthreads();
    buf ^= 1;
  }
}

// ---------------------------------------------------------------------------
// Split helpers: fp32 -> bf16 hi + bf16 lo (lo = bf16(x - float(hi)))
// ---------------------------------------------------------------------------
__device__ __forceinline__ void split2(float v, __nv_bfloat16& h,
                                       __nv_bfloat16& l) {
  h = __float2bfloat16(v);
  l = __float2bfloat16(v - __bfloat162float(h));
}
__device__ __forceinline__ uint32_t pack_bf(__nv_bfloat16 a, __nv_bfloat16 b) {
  return (uint32_t)__bfloat16_as_ushort(a) |
         ((uint32_t)__bfloat16_as_ushort(b) << 16);
}

__global__ __launch_bounds__(256) void split_x_kernel(const float* __restrict__ x) {
  int i = (blockIdx.x * 256 + threadIdx.x) << 2;
  float4 v = *(const float4*)(x + i);
  __nv_bfloat16 h0, h1, h2, h3, l0, l1, l2, l3;
  split2(v.x, h0, l0); split2(v.y, h1, l1);
  split2(v.z, h2, l2); split2(v.w, h3, l3);
  *(uint2*)(&g_xhi[i]) = make_uint2(pack_bf(h0, h1), pack_bf(h2, h3));
  *(uint2*)(&g_xlo[i]) = make_uint2(pack_bf(l0, l1), pack_bf(l2, l3));
}

__global__ __launch_bounds__(256) void split_w_kernel(
    const float* __restrict__ wq, const float* __restrict__ wk,
    const float* __restrict__ wv) {
  int wsel = blockIdx.y;
  const float* src = (wsel == 0) ? wq : (wsel == 1) ? wk : wv;
  int i = (blockIdx.x * 256 + threadIdx.x) << 2;
  float4 v = *(const float4*)(src + i);
  __nv_bfloat16 h0, h1, h2, h3, l0, l1, l2, l3;
  split2(v.x, h0, l0); split2(v.y, h1, l1);
  split2(v.z, h2, l2); split2(v.w, h3, l3);
  int o = wsel * (H * D) + i;
  *(uint2*)(&g_whi[o]) = make_uint2(pack_bf(h0, h1), pack_bf(h2, h3));
  *(uint2*)(&g_wlo[o]) = make_uint2(pack_bf(l0, l1), pack_bf(l2, l3));
}

// ---------------------------------------------------------------------------
// QKV: C[128,128] = X[128tile,2048] @ W^T via HMMA, outputs re-split hi/lo.
// grid (32 m-tiles, 3 weights).
// ---------------------------------------------------------------------------
__global__ __launch_bounds__(256) void qkv_mma_kernel() {
  extern __shared__ __align__(16) char sm[];
  uint32_t sb = smem_u32(sm);
  const int mt = blockIdx.x, wsel = blockIdx.y;

  GemmArgs g;
  g.ahi = g_xhi; g.alo = g_xlo; g.arow0 = mt * 128; g.astride = D;
  g.bhi = g_whi + wsel * (H * D); g.blo = g_wlo + wsel * (H * D);
  g.brow0 = 0; g.bstride = D; g.col0 = 0; g.nchunks = D / 64;

  float acc[4][4][4] = {};
  gemm_mainloop(acc, g, sb);

  const int l = threadIdx.x & 31, w = threadIdx.x >> 5;
  const int wm = w & 1, wn = w >> 1;
#pragma unroll
  for (int mi = 0; mi < 4; mi++) {
#pragma unroll
    for (int nj = 0; nj < 4; nj++) {
      int r0 = mt * 128 + wm * 64 + mi * 16 + (l >> 2);
      int c0 = wn * 32 + nj * 8 + ((l & 3) << 1);
      const float* cc = acc[mi][nj];
#pragma unroll
      for (int hh = 0; hh < 2; hh++) {
        int tok = r0 + hh * 8;
        __nv_bfloat16 h0, l0, h1, l1;
        split2(cc[hh * 2 + 0], h0, l0);
        split2(cc[hh * 2 + 1], h1, l1);
        if (wsel == 0) {
          *(uint32_t*)&g_qhi[tok * H + c0] = pack_bf(h0, h1);
          *(uint32_t*)&g_qlo[tok * H + c0] = pack_bf(l0, l1);
        } else if (wsel == 1) {
          *(uint32_t*)&g_khi[tok * H + c0] = pack_bf(h0, h1);
          *(uint32_t*)&g_klo[tok * H + c0] = pack_bf(l0, l1);
        } else {
          g_vhiT[(size_t)c0 * T + tok] = h0;
          g_vhiT[(size_t)(c0 + 1) * T + tok] = h1;
          g_vloT[(size_t)c0 * T + tok] = l0;
          g_vloT[(size_t)(c0 + 1) * T + tok] = l1;
        }
      }
    }
  }
}

// ---------------------------------------------------------------------------
// Scores: S = Q_it @ K_jt^T * scale, causal mask -> -inf, fp32 out.
// grid (jt=32, it=32); jt>it exits.
// ---------------------------------------------------------------------------
__global__ __launch_bounds__(256) void scores_mma_kernel() {
  const int jt = blockIdx.x, it = blockIdx.y;
  if (jt > it) return;
  extern __shared__ __align__(16) char sm[];
  uint32_t sb = smem_u32(sm);

  GemmArgs g;
  g.ahi = g_qhi; g.alo = g_qlo; g.arow0 = it * 128; g.astride = H;
  g.bhi = g_khi; g.blo = g_klo; g.brow0 = jt * 128; g.bstride = H;
  g.col0 = 0; g.nchunks = H / 64;

  float acc[4][4][4] = {};
  gemm_mainloop(acc, g, sb);

  const int l = threadIdx.x & 31, w = threadIdx.x >> 5;
  const int wm = w & 1, wn = w >> 1;
  const float scale = 0.08838834764831845f;  // 1/sqrt(128)
#pragma unroll
  for (int mi = 0; mi < 4; mi++) {
#pragma unroll
    for (int nj = 0; nj < 4; nj++) {
      int r0 = it * 128 + wm * 64 + mi * 16 + (l >> 2);
      int c0 = jt * 128 + wn * 32 + nj * 8 + ((l & 3) << 1);
      const float* cc = acc[mi][nj];
#pragma unroll
      for (int hh = 0; hh < 2; hh++) {
        int row = r0 + hh * 8;
        float2 v;
        v.x = (c0 + 0 > row) ? -INFINITY : cc[hh * 2 + 0] * scale;
        v.y = (c0 + 1 > row) ? -INFINITY : cc[hh * 2 + 1] * scale;
        *(float2*)(g_s + (size_t)row * T + c0) = v;
      }
    }
  }
}

// ---------------------------------------------------------------------------
// Softmax: fp32 logits -> probabilities re-split to bf16 hi/lo. 1 block/row.
// ---------------------------------------------------------------------------
__global__ __launch_bounds__(256) void softmax_kernel() {
  const int t = blockIdx.x;
  const int ncols = ((t >> 7) + 1) << 7;  // 128-tile-aligned causal end
  const float* row = g_s + (size_t)t * T;
  const int tid = threadIdx.x;

  float vals[16];
  float lmax = -INFINITY;
#pragma unroll
  for (int p = 0; p < 16; p++) {
    int c = tid + (p << 8);
    float v = (c < ncols) ? row[c] : -INFINITY;
    vals[p] = v;
    lmax = fmaxf(lmax, v);
  }

  __shared__ float redm[8];
#pragma unroll
  for (int o = 16; o; o >>= 1) lmax = fmaxf(lmax, __shfl_xor_sync(~0u, lmax, o));
  if ((tid & 31) == 0) redm[tid >> 5] = lmax;
  __syncthreads();
  float m = redm[0];
#pragma unroll
  for (int w = 1; w < 8; w++) m = fmaxf(m, redm[w]);

  float lsum = 0.f;
#pragma unroll
  for (int p = 0; p < 16; p++) {
    float e = __expf(vals[p] - m);
    vals[p] = e;
    lsum += e;
  }

  __shared__ float reds[8];
#pragma unroll
  for (int o = 16; o; o >>= 1) lsum += __shfl_xor_sync(~0u, lsum, o);
  if ((tid & 31) == 0) reds[tid >> 5] = lsum;
  __syncthreads();
  float s = 0.f;
#pragma unroll
  for (int w = 0; w < 8; w++) s += reds[w];

  float inv = 1.0f / s;
  __nv_bfloat16* rh = g_phi + (size_t)t * T;
  __nv_bfloat16* rl = g_plo + (size_t)t * T;
#pragma unroll
  for (int p = 0; p < 16; p++) {
    int c = tid + (p << 8);
    if (c < ncols) {
      __nv_bfloat16 h, l;
      split2(vals[p] * inv, h, l);
      rh[c] = h;
      rl[c] = l;
    }
  }
}

// ---------------------------------------------------------------------------
// PV: partial O = P @ V (split-K chunks of 512 kv positions) via HMMA.
// grid (ch=8, it=32); chunks beyond causal end exit.
// ---------------------------------------------------------------------------
__global__ __launch_bounds__(256) void pv_mma_kernel() {
  const int ch = blockIdx.x, it = blockIdx.y;
  const int kbeg = ch << 9;
  const int klim = (it + 1) << 7;
  if (kbeg >= klim) return;
  const int kend = min(kbeg + 512, klim);
  extern __shared__ __align__(16) char sm[];
  uint32_t sb = smem_u32(sm);

  GemmArgs g;
  g.ahi = g_phi; g.alo = g_plo; g.arow0 = it * 128; g.astride = T;
  g.bhi = g_vhiT; g.blo = g_vloT; g.brow0 = 0; g.bstride = T;
  g.col0 = kbeg; g.nchunks = (kend - kbeg) >> 6;

  float acc[4][4][4] = {};
  gemm_mainloop(acc, g, sb);

  const int l = threadIdx.x & 31, w = threadIdx.x >> 5;
  const int wm = w & 1, wn = w >> 1;
  float* op = g_part[ch];
#pragma unroll
  for (int mi = 0; mi < 4; mi++) {
#pragma unroll
    for (int nj = 0; nj < 4; nj++) {
      int r0 = it * 128 + wm * 64 + mi * 16 + (l >> 2);
      int c0 = wn * 32 + nj * 8 + ((l & 3) << 1);
      const float* cc = acc[mi][nj];
#pragma unroll
      for (int hh = 0; hh < 2; hh++) {
        int row = r0 + hh * 8;
        *(float2*)(op + (size_t)row * H + c0) =
            make_float2(cc[hh * 2 + 0], cc[hh * 2 + 1]);
      }
    }
  }
}

// ---------------------------------------------------------------------------
// Reduce split-K partials (fixed order, only valid chunks per row).
// ---------------------------------------------------------------------------
__global__ __launch_bounds__(256) void reduce_kernel(float* __restrict__ out) {
  int idx = blockIdx.x * 256 + threadIdx.x;  // 0..524287
  int t = idx >> 7;
  int nch = (t >> 9) + 1;
  float s = 0.f;
  for (int c = 0; c < nch; c++) s += g_part[c][idx];
  out[idx] = s;
}

// ---------------------------------------------------------------------------
extern "C" void kernel_launch(void* const* d_in, const int* in_sizes, int n_in,
                              void* d_out, int out_size) {
  (void)in_sizes; (void)n_in; (void)out_size;
  const float* x = (const float*)d_in[0];
  const float* wq = (const float*)d_in[1];
  const float* wk = (const float*)d_in[2];
  const float* wv = (const float*)d_in[3];
  float* out = (float*)d_out;

  cudaFuncSetAttribute(qkv_mma_kernel,
                       cudaFuncAttributeMaxDynamicSharedMemorySize, SMEM_BYTES);
  cudaFuncSetAttribute(scores_mma_kernel,
                       cudaFuncAttributeMaxDynamicSharedMemorySize, SMEM_BYTES);
  cudaFuncSetAttribute(pv_mma_kernel,
                       cudaFuncAttributeMaxDynamicSharedMemorySize, SMEM_BYTES);

  split_x_kernel<<<(T * D / 4) / 256, 256>>>(x);
  split_w_kernel<<<dim3((H * D / 4) / 256, 3), 256>>>(wq, wk, wv);
  qkv_mma_kernel<<<dim3(32, 3), 256, SMEM_BYTES>>>();
  scores_mma_kernel<<<dim3(32, 32), 256, SMEM_BYTES>>>();
  softmax_kernel<<<T, 256>>>();
  pv_mma_kernel<<<dim3(8, 32), 256, SMEM_BYTES>>>();
  reduce_kernel<<<(T * H) / 256, 256>>>(out);
}